// round 2
// baseline (speedup 1.0000x reference)
#include <cuda_runtime.h>

#define TT 512
#define BB 512
#define DD 16
#define HH 64
#define G3 192          // 3*H
#define RR 2            // batch rows per recurrent CTA
#define PT 16           // timesteps per precompute CTA

typedef unsigned long long ull;

__device__ __forceinline__ ull fma2(ull a, ull b, ull c) {
    ull d;
    asm("fma.rn.f32x2 %0, %1, %2, %3;" : "=l"(d) : "l"(a), "l"(b), "l"(c));
    return d;
}
__device__ __forceinline__ float hadd2(ull a) {
    return __uint_as_float((unsigned)a) + __uint_as_float((unsigned)(a >> 32));
}
__device__ __forceinline__ float sigf(float x) {
    return __fdividef(1.f, 1.f + __expf(-x));
}
__device__ __forceinline__ float tanhfast(float x) {
    return __fdividef(2.f, 1.f + __expf(-2.f * x)) - 1.f;
}

// scratch: precomputed input projections xg[b][t][g] (includes b_ih)
__device__ float g_xg[(size_t)BB * TT * G3];

// ---------------------------------------------------------------------------
// Kernel 1: xg = x @ w_ih^T + b_ih for all (b,t).  805M FMA, write 201MB.
// ---------------------------------------------------------------------------
__global__ __launch_bounds__(G3)
void xg_kernel(const float* __restrict__ x,
               const float* __restrict__ w_ih,
               const float* __restrict__ b_ih)
{
    __shared__ __align__(16) float xs[PT][DD];
    const int g  = threadIdx.x;
    const int b  = blockIdx.y;
    const int t0 = blockIdx.x * PT;

    ulonglong2 wv[DD / 4];
    {
        const ulonglong2* p = (const ulonglong2*)(w_ih + g * DD);
        #pragma unroll
        for (int j = 0; j < DD / 4; j++) wv[j] = p[j];
    }
    const float bias = b_ih[g];

    for (int i = g; i < PT * DD; i += G3)
        xs[i / DD][i % DD] = x[((size_t)b * TT + t0 + i / DD) * DD + i % DD];
    __syncthreads();

    #pragma unroll 4
    for (int tt = 0; tt < PT; tt++) {
        const ulonglong2* xp = (const ulonglong2*)xs[tt];
        ull a0 = 0ull, a1 = 0ull;
        #pragma unroll
        for (int j = 0; j < DD / 4; j++) {
            ulonglong2 xv = xp[j];
            a0 = fma2(wv[j].x, xv.x, a0);
            a1 = fma2(wv[j].y, xv.y, a1);
        }
        g_xg[((size_t)b * TT + t0 + tt) * G3 + g] = hadd2(a0) + hadd2(a1) + bias;
    }
}

// ---------------------------------------------------------------------------
// Kernel 2: forward recurrence (k-split 2, 2 units/thread) + epilogue.
// Thread (s = warp&1, l = lane): owns units u0=l, u1=l+32, k-range [32s,32s+32).
// Weight regs: 6 half-rows x 32 f32 = 192 regs.
// ---------------------------------------------------------------------------
__global__ __launch_bounds__(64 * RR, 2)
void gru_rec_kernel(const float* __restrict__ w_hh,
                    const float* __restrict__ b_hh,
                    const float* __restrict__ x,
                    const float* __restrict__ w_ih_b,
                    const float* __restrict__ b_ih_b,
                    const float* __restrict__ b_hh_b,
                    const float* __restrict__ fc_w,
                    const float* __restrict__ fc_b,
                    float* __restrict__ out)
{
    __shared__ __align__(16) float h_sh[2][RR][HH];
    __shared__ float part_sh[RR][6][32];
    __shared__ float red_sh[RR][HH];

    const int tid = threadIdx.x;
    const int r   = tid >> 6;          // batch row within CTA
    const int s   = (tid >> 5) & 1;    // k-split (warp-uniform)
    const int l   = tid & 31;
    const int b   = blockIdx.x * RR + r;

    // rows this thread owns: (r,z,n) of unit l and of unit l+32
    // row order i: 0:r(u0) 1:z(u0) 2:n(u0) 3:r(u1) 4:z(u1) 5:n(u1)
    ulonglong2 w[6][8];                // 6 x 32 floats
    {
        const int rows[6] = { l, HH + l, 2 * HH + l,
                              32 + l, HH + 32 + l, 2 * HH + 32 + l };
        #pragma unroll
        for (int i = 0; i < 6; i++) {
            const ulonglong2* p = (const ulonglong2*)(w_hh + rows[i] * HH + 32 * s);
            #pragma unroll
            for (int j = 0; j < 8; j++) w[i][j] = p[j];
        }
    }
    const float bhr0 = b_hh[l],      bhz0 = b_hh[HH + l],      bhn0 = b_hh[2 * HH + l];
    const float bhr1 = b_hh[32 + l], bhz1 = b_hh[HH + 32 + l], bhn1 = b_hh[2 * HH + 32 + l];

    // xg pointer for this batch row; row offsets are compile-time immediates from base+l
    const float* xgp = g_xg + (size_t)b * TT * G3 + l;

    // init h = 0
    h_sh[0][r][s * 32 + l] = 0.f;

    // preload xg(t=0) on split-0
    float cur0 = 0.f, cur1 = 0.f, cur2 = 0.f, cur3 = 0.f, cur4 = 0.f, cur5 = 0.f;
    if (s == 0) {
        cur0 = xgp[0];        cur1 = xgp[HH];        cur2 = xgp[2 * HH];
        cur3 = xgp[32];       cur4 = xgp[HH + 32];   cur5 = xgp[2 * HH + 32];
    }
    __syncthreads();

    int p = 0;
    for (int t = 0; t < TT; ++t) {
        // prefetch xg(t+1) (split-0); consumed after next barrier
        float nx0 = 0.f, nx1 = 0.f, nx2 = 0.f, nx3 = 0.f, nx4 = 0.f, nx5 = 0.f;
        if (s == 0 && t + 1 < TT) {
            const float* q = xgp + (size_t)(t + 1) * G3;
            nx0 = q[0];      nx1 = q[HH];      nx2 = q[2 * HH];
            nx3 = q[32];     nx4 = q[HH + 32]; nx5 = q[2 * HH + 32];
        }

        // partial dot products over this thread's k-half
        const ulonglong2* hp = (const ulonglong2*)&h_sh[p][r][32 * s];
        ull a[6] = {0ull, 0ull, 0ull, 0ull, 0ull, 0ull};
        #pragma unroll
        for (int j = 0; j < 8; j++) {
            ulonglong2 hv = hp[j];
            #pragma unroll
            for (int i = 0; i < 6; i++) {
                a[i] = fma2(w[i][j].x, hv.x, a[i]);
                a[i] = fma2(w[i][j].y, hv.y, a[i]);
            }
        }
        float part[6];
        #pragma unroll
        for (int i = 0; i < 6; i++) part[i] = hadd2(a[i]);

        if (s == 1) {
            #pragma unroll
            for (int i = 0; i < 6; i++) part_sh[r][i][l] = part[i];
        }
        __syncthreads();                       // partials visible

        if (s == 0) {
            float hr0 = part[0] + part_sh[r][0][l] + bhr0;
            float hz0 = part[1] + part_sh[r][1][l] + bhz0;
            float hn0 = part[2] + part_sh[r][2][l] + bhn0;
            float hr1 = part[3] + part_sh[r][3][l] + bhr1;
            float hz1 = part[4] + part_sh[r][4][l] + bhz1;
            float hn1 = part[5] + part_sh[r][5][l] + bhn1;

            float rr0 = sigf(cur0 + hr0);
            float zz0 = sigf(cur1 + hz0);
            float nn0 = tanhfast(cur2 + rr0 * hn0);
            float ho0 = h_sh[p][r][l];
            h_sh[p ^ 1][r][l] = (1.f - zz0) * nn0 + zz0 * ho0;

            float rr1 = sigf(cur3 + hr1);
            float zz1 = sigf(cur4 + hz1);
            float nn1 = tanhfast(cur5 + rr1 * hn1);
            float ho1 = h_sh[p][r][32 + l];
            h_sh[p ^ 1][r][32 + l] = (1.f - zz1) * nn1 + zz1 * ho1;
        }
        __syncthreads();                       // h(t+1) visible

        cur0 = nx0; cur1 = nx1; cur2 = nx2;
        cur3 = nx3; cur4 = nx4; cur5 = nx5;
        p ^= 1;
    }

    // ---- epilogue: backward GRU = ONE step from h=0 on x[:,T-1,:]; then fc ----
    {
        const int j  = tid & 63;
        const int rr = tid >> 6;
        const int bb = blockIdx.x * RR + rr;
        const float* xl = x + ((size_t)bb * TT + (TT - 1)) * DD;
        float xv[DD];
        #pragma unroll
        for (int k = 0; k < DD; k++) xv[k] = __ldg(xl + k);

        float ar  = __ldg(b_ih_b + j)          + __ldg(b_hh_b + j);
        float az  = __ldg(b_ih_b + HH + j)     + __ldg(b_hh_b + HH + j);
        float anx = __ldg(b_ih_b + 2 * HH + j);
        float anh = __ldg(b_hh_b + 2 * HH + j);
        const float* wr = w_ih_b + (size_t)j * DD;
        const float* wz = w_ih_b + (size_t)(HH + j) * DD;
        const float* wn = w_ih_b + (size_t)(2 * HH + j) * DD;
        #pragma unroll
        for (int k = 0; k < DD; k++) {
            ar  += __ldg(wr + k) * xv[k];
            az  += __ldg(wz + k) * xv[k];
            anx += __ldg(wn + k) * xv[k];
        }
        float rb = sigf(ar);
        float zb = sigf(az);
        float nb = tanhfast(anx + rb * anh);
        float hb = (1.f - zb) * nb;            // h_prev = 0

        red_sh[rr][j] = h_sh[p][rr][j] * __ldg(fc_w + j) + hb * __ldg(fc_w + HH + j);
    }
    __syncthreads();
    if (tid < RR) {
        float sum = __ldg(fc_b);
        #pragma unroll
        for (int k = 0; k < HH; k++) sum += red_sh[tid][k];
        out[blockIdx.x * RR + tid] = sum;
    }
}

extern "C" void kernel_launch(void* const* d_in, const int* in_sizes, int n_in,
                              void* d_out, int out_size)
{
    const float* x      = (const float*)d_in[0];
    const float* w_ih_f = (const float*)d_in[1];
    const float* w_hh_f = (const float*)d_in[2];
    const float* b_ih_f = (const float*)d_in[3];
    const float* b_hh_f = (const float*)d_in[4];
    const float* w_ih_b = (const float*)d_in[5];
    /* d_in[6] = w_hh_b unused: backward direction starts from h=0 */
    const float* b_ih_b = (const float*)d_in[7];
    const float* b_hh_b = (const float*)d_in[8];
    const float* fc_w   = (const float*)d_in[9];
    const float* fc_b   = (const float*)d_in[10];

    xg_kernel<<<dim3(TT / PT, BB), G3>>>(x, w_ih_f, b_ih_f);
    gru_rec_kernel<<<BB / RR, 64 * RR>>>(w_hh_f, b_hh_f, x,
                                         w_ih_b, b_ih_b, b_hh_b,
                                         fc_w, fc_b, (float*)d_out);
}

// round 3
// speedup vs baseline: 1.0771x; 1.0771x over previous
#include <cuda_runtime.h>

#define TT 512
#define BB 512
#define DD 16
#define HH 64
#define G3 192
#define PT 32          // timesteps per precompute CTA

typedef unsigned long long ull;

__device__ __forceinline__ ull fma2(ull a, ull b, ull c) {
    ull d;
    asm("fma.rn.f32x2 %0, %1, %2, %3;" : "=l"(d) : "l"(a), "l"(b), "l"(c));
    return d;
}
__device__ __forceinline__ float hadd2(ull a) {
    return __uint_as_float((unsigned)a) + __uint_as_float((unsigned)(a >> 32));
}
__device__ __forceinline__ float tanha(float x) {
    float y;
    asm("tanh.approx.f32 %0, %1;" : "=f"(y) : "f"(x));
    return y;
}
__device__ __forceinline__ float siga(float x) {   // sigmoid via tanh
    return fmaf(0.5f, tanha(0.5f * x), 0.5f);
}

// scratch: precomputed input projections xg[b][t][g] (includes b_ih)
__device__ float g_xg[(size_t)BB * TT * G3];

// ---------------------------------------------------------------------------
// Kernel 1: xg = x @ w_ih^T + b_ih for all (b,t).
// ---------------------------------------------------------------------------
__global__ __launch_bounds__(G3)
void xg_kernel(const float* __restrict__ x,
               const float* __restrict__ w_ih,
               const float* __restrict__ b_ih)
{
    __shared__ __align__(16) float xs[PT][DD];
    const int g  = threadIdx.x;
    const int b  = blockIdx.y;
    const int t0 = blockIdx.x * PT;

    ulonglong2 wv[DD / 4];
    {
        const ulonglong2* p = (const ulonglong2*)(w_ih + g * DD);
        #pragma unroll
        for (int j = 0; j < DD / 4; j++) wv[j] = p[j];
    }
    const float bias = b_ih[g];

    for (int i = g; i < PT * DD / 4; i += G3)
        ((float4*)&xs[0][0])[i] =
            ((const float4*)(x + ((size_t)b * TT + t0) * DD))[i];
    __syncthreads();

    #pragma unroll 8
    for (int tt = 0; tt < PT; tt++) {
        const ulonglong2* xp = (const ulonglong2*)xs[tt];
        ull a0 = 0ull, a1 = 0ull;
        #pragma unroll
        for (int j = 0; j < DD / 4; j++) {
            ulonglong2 xv = xp[j];
            a0 = fma2(wv[j].x, xv.x, a0);
            a1 = fma2(wv[j].y, xv.y, a1);
        }
        g_xg[((size_t)b * TT + t0 + tt) * G3 + g] = hadd2(a0) + hadd2(a1) + bias;
    }
}

// ---------------------------------------------------------------------------
// Kernel 2: forward recurrence. CTA = 64 threads = 1 batch row, grid 512.
// Warp s (s=0,1): k-half [32s,32s+32), finalizes units [32s,32s+32).
// Lane l computes partials for units l and l+32 (6 gate-rows) over its k-half,
// exports the 3 partials for the unit the OTHER warp finalizes, keeps its own.
// One CTA barrier per step; h stays warp-local (syncwarp only).
// ---------------------------------------------------------------------------
__global__ __launch_bounds__(64, 4)
void gru_rec_kernel(const float* __restrict__ w_hh,
                    const float* __restrict__ b_hh,
                    const float* __restrict__ x,
                    const float* __restrict__ w_ih_b,
                    const float* __restrict__ b_ih_b,
                    const float* __restrict__ b_hh_b,
                    const float* __restrict__ fc_w,
                    const float* __restrict__ fc_b,
                    float* __restrict__ out)
{
    __shared__ __align__(16) float h_sh[HH];
    __shared__ float part_sh[2][2][3][32];   // [parity][src warp][row][lane]
    __shared__ float red_sh[HH];

    const int tid = threadIdx.x;
    const int s   = tid >> 5;        // warp = k-half = unit-half
    const int l   = tid & 31;
    const int b   = blockIdx.x;
    const int u   = 32 * s + l;      // unit this thread finalizes

    // weights: rows (r,z,n) of unit l and unit l+32, k-range [32s, 32s+32)
    // order i: 0:r(l) 1:z(l) 2:n(l) 3:r(32+l) 4:z(32+l) 5:n(32+l)
    ulonglong2 w[6][8];
    {
        const int rows[6] = { l, HH + l, 2 * HH + l,
                              32 + l, HH + 32 + l, 2 * HH + 32 + l };
        #pragma unroll
        for (int i = 0; i < 6; i++) {
            const ulonglong2* p = (const ulonglong2*)(w_hh + rows[i] * HH + 32 * s);
            #pragma unroll
            for (int j = 0; j < 8; j++) w[i][j] = p[j];
        }
    }
    const float bhr = b_hh[u];
    const float bhz = b_hh[HH + u];
    const float bhn = b_hh[2 * HH + u];

    const float* xgp = g_xg + (size_t)b * TT * G3;

    float hold = 0.f;
    h_sh[u] = 0.f;
    float cur0 = xgp[u];
    float cur1 = xgp[HH + u];
    float cur2 = xgp[2 * HH + u];
    __syncthreads();

    const int eo = s ? 0 : 3;   // rows exported to the other warp
    const int ko = s ? 3 : 0;   // rows kept for own finalize

    int p = 0;
    for (int t = 0; t < TT; ++t) {
        // prefetch xg(t+1); consumed after the barrier next iteration
        float nx0 = 0.f, nx1 = 0.f, nx2 = 0.f;
        if (t + 1 < TT) {
            const float* q = xgp + (size_t)(t + 1) * G3;
            nx0 = q[u]; nx1 = q[HH + u]; nx2 = q[2 * HH + u];
        }

        // partial dots over this warp's k-half (h values are warp-local)
        const ulonglong2* hp = (const ulonglong2*)&h_sh[32 * s];
        ull a[6] = {0ull, 0ull, 0ull, 0ull, 0ull, 0ull};
        #pragma unroll
        for (int j = 0; j < 8; j++) {
            ulonglong2 hv = hp[j];
            #pragma unroll
            for (int i = 0; i < 6; i++) {
                a[i] = fma2(w[i][j].x, hv.x, a[i]);
                a[i] = fma2(w[i][j].y, hv.y, a[i]);
            }
        }
        float prt[6];
        #pragma unroll
        for (int i = 0; i < 6; i++) prt[i] = hadd2(a[i]);

        // export the counterpart's 3 partials
        part_sh[p][s][0][l] = prt[eo + 0];
        part_sh[p][s][1][l] = prt[eo + 1];
        part_sh[p][s][2][l] = prt[eo + 2];
        __syncthreads();

        // finalize own unit
        float sr = prt[ko + 0] + part_sh[p][s ^ 1][0][l] + bhr;
        float sz = prt[ko + 1] + part_sh[p][s ^ 1][1][l] + bhz;
        float sh = prt[ko + 2] + part_sh[p][s ^ 1][2][l] + bhn;

        float rr = siga(cur0 + sr);
        float zz = siga(cur1 + sz);
        float nn = tanha(cur2 + rr * sh);
        hold = (1.f - zz) * nn + zz * hold;

        h_sh[u] = hold;          // own-warp region only
        __syncwarp();

        cur0 = nx0; cur1 = nx1; cur2 = nx2;
        p ^= 1;
    }
    __syncthreads();

    // ---- epilogue: backward GRU = ONE step from h=0 on x[:,T-1,:]; then fc ----
    {
        const int j = tid;  // unit 0..63
        const float* xl = x + ((size_t)b * TT + (TT - 1)) * DD;
        float xv[DD];
        #pragma unroll
        for (int k = 0; k < DD; k++) xv[k] = __ldg(xl + k);

        float ar  = __ldg(b_ih_b + j)          + __ldg(b_hh_b + j);
        float az  = __ldg(b_ih_b + HH + j)     + __ldg(b_hh_b + HH + j);
        float anx = __ldg(b_ih_b + 2 * HH + j);
        float anh = __ldg(b_hh_b + 2 * HH + j);
        const float* wr = w_ih_b + (size_t)j * DD;
        const float* wz = w_ih_b + (size_t)(HH + j) * DD;
        const float* wn = w_ih_b + (size_t)(2 * HH + j) * DD;
        #pragma unroll
        for (int k = 0; k < DD; k++) {
            ar  += __ldg(wr + k) * xv[k];
            az  += __ldg(wz + k) * xv[k];
            anx += __ldg(wn + k) * xv[k];
        }
        float rb = siga(ar);
        float zb = siga(az);
        float nb = tanha(anx + rb * anh);
        float hb = (1.f - zb) * nb;            // h_prev = 0

        red_sh[j] = h_sh[j] * __ldg(fc_w + j) + hb * __ldg(fc_w + HH + j);
    }
    __syncthreads();
    if (tid == 0) {
        float sum = __ldg(fc_b);
        #pragma unroll
        for (int k = 0; k < HH; k++) sum += red_sh[k];
        out[b] = sum;
    }
}

extern "C" void kernel_launch(void* const* d_in, const int* in_sizes, int n_in,
                              void* d_out, int out_size)
{
    const float* x      = (const float*)d_in[0];
    const float* w_ih_f = (const float*)d_in[1];
    const float* w_hh_f = (const float*)d_in[2];
    const float* b_ih_f = (const float*)d_in[3];
    const float* b_hh_f = (const float*)d_in[4];
    const float* w_ih_b = (const float*)d_in[5];
    /* d_in[6] = w_hh_b unused: backward direction starts from h=0 */
    const float* b_ih_b = (const float*)d_in[7];
    const float* b_hh_b = (const float*)d_in[8];
    const float* fc_w   = (const float*)d_in[9];
    const float* fc_b   = (const float*)d_in[10];

    xg_kernel<<<dim3(TT / PT, BB), G3>>>(x, w_ih_f, b_ih_f);
    gru_rec_kernel<<<BB, 64>>>(w_hh_f, b_hh_f, x,
                               w_ih_b, b_ih_b, b_hh_b,
                               fc_w, fc_b, (float*)d_out);
}

// round 4
// speedup vs baseline: 1.4117x; 1.3107x over previous
#include <cuda_runtime.h>
#include <cuda_fp16.h>

#define TT 512
#define BB 512
#define DD 16
#define HH 64
#define G3 192
#define PT 32          // timesteps per precompute CTA
#define BK 8           // timesteps per staged block in rec kernel
#define NBK (TT / BK)

typedef unsigned long long ull;

__device__ __forceinline__ ull fma2(ull a, ull b, ull c) {
    ull d;
    asm("fma.rn.f32x2 %0, %1, %2, %3;" : "=l"(d) : "l"(a), "l"(b), "l"(c));
    return d;
}
__device__ __forceinline__ float hadd2(ull a) {
    return __uint_as_float((unsigned)a) + __uint_as_float((unsigned)(a >> 32));
}
__device__ __forceinline__ float tanha(float x) {
    float y;
    asm("tanh.approx.f32 %0, %1;" : "=f"(y) : "f"(x));
    return y;
}
__device__ __forceinline__ float siga(float x) {
    return fmaf(0.5f, tanha(0.5f * x), 0.5f);
}
__device__ __forceinline__ void cpa16(unsigned smem, const void* gmem) {
    asm volatile("cp.async.ca.shared.global [%0], [%1], 16;\n"
                 :: "r"(smem), "l"(gmem));
}
__device__ __forceinline__ void cpa_commit() {
    asm volatile("cp.async.commit_group;\n" ::: "memory");
}
__device__ __forceinline__ void cpa_wait1() {
    asm volatile("cp.async.wait_group 1;\n" ::: "memory");
}

// scratch: precomputed input projections xg[b][t][g] (includes b_ih), fp16
__device__ __half g_xg[(size_t)BB * TT * G3];

// ---------------------------------------------------------------------------
// Kernel 1: xg = x @ w_ih^T + b_ih for all (b,t), stored fp16.
// ---------------------------------------------------------------------------
__global__ __launch_bounds__(G3)
void xg_kernel(const float* __restrict__ x,
               const float* __restrict__ w_ih,
               const float* __restrict__ b_ih)
{
    __shared__ __align__(16) float xs[PT][DD];
    const int g  = threadIdx.x;
    const int b  = blockIdx.y;
    const int t0 = blockIdx.x * PT;

    ulonglong2 wv[DD / 4];
    {
        const ulonglong2* p = (const ulonglong2*)(w_ih + g * DD);
        #pragma unroll
        for (int j = 0; j < DD / 4; j++) wv[j] = p[j];
    }
    const float bias = b_ih[g];

    for (int i = g; i < PT * DD / 4; i += G3)
        ((float4*)&xs[0][0])[i] =
            ((const float4*)(x + ((size_t)b * TT + t0) * DD))[i];
    __syncthreads();

    #pragma unroll 8
    for (int tt = 0; tt < PT; tt++) {
        const ulonglong2* xp = (const ulonglong2*)xs[tt];
        ull a0 = 0ull, a1 = 0ull;
        #pragma unroll
        for (int j = 0; j < DD / 4; j++) {
            ulonglong2 xv = xp[j];
            a0 = fma2(wv[j].x, xv.x, a0);
            a1 = fma2(wv[j].y, xv.y, a1);
        }
        g_xg[((size_t)b * TT + t0 + tt) * G3 + g] =
            __float2half_rn(hadd2(a0) + hadd2(a1) + bias);
    }
}

// ---------------------------------------------------------------------------
// Kernel 2: forward recurrence. CTA = 64 threads = 1 batch row, grid 512.
// Warp s: k-half [32s,32s+32), finalizes units [32s,32s+32). One CTA barrier
// per step. xg staged into SMEM in 8-step blocks via cp.async (fp16).
// ---------------------------------------------------------------------------
__global__ __launch_bounds__(64, 4)
void gru_rec_kernel(const float* __restrict__ w_hh,
                    const float* __restrict__ b_hh,
                    const float* __restrict__ x,
                    const float* __restrict__ w_ih_b,
                    const float* __restrict__ b_ih_b,
                    const float* __restrict__ b_hh_b,
                    const float* __restrict__ fc_w,
                    const float* __restrict__ fc_b,
                    float* __restrict__ out)
{
    __shared__ __align__(16) float h_sh[HH];
    __shared__ float part_sh[2][2][3][32];     // [parity][src warp][row][lane]
    __shared__ __align__(16) __half xg_sh[2][BK][G3];   // staged blocks (3KB ea)
    __shared__ float red_sh[HH];

    const int tid = threadIdx.x;
    const int s   = tid >> 5;
    const int l   = tid & 31;
    const int b   = blockIdx.x;
    const int u   = 32 * s + l;

    // weights: rows (r,z,n) of unit l and unit l+32, k-range [32s, 32s+32)
    ulonglong2 w[6][8];
    {
        const int rows[6] = { l, HH + l, 2 * HH + l,
                              32 + l, HH + 32 + l, 2 * HH + 32 + l };
        #pragma unroll
        for (int i = 0; i < 6; i++) {
            const ulonglong2* p = (const ulonglong2*)(w_hh + rows[i] * HH + 32 * s);
            #pragma unroll
            for (int j = 0; j < 8; j++) w[i][j] = p[j];
        }
    }
    const float bhr = b_hh[u];
    const float bhz = b_hh[HH + u];
    const float bhn = b_hh[2 * HH + u];

    const char* xg_gbase = (const char*)(g_xg + (size_t)b * TT * G3);
    // per-block staged bytes: BK*G3*2 = 3072 = 192 chunks of 16B; 3 per thread
    unsigned xg_s0 = (unsigned)__cvta_generic_to_shared(&xg_sh[0][0][0]);
    unsigned xg_s1 = (unsigned)__cvta_generic_to_shared(&xg_sh[1][0][0]);

    float hold = 0.f;
    h_sh[u] = 0.f;

    // prologue: stage block 0
    {
        const char* src = xg_gbase;
        #pragma unroll
        for (int c = 0; c < 3; c++)
            cpa16(xg_s0 + (tid + 64 * c) * 16, src + (tid + 64 * c) * 16);
        cpa_commit();
    }
    __syncthreads();

    const int eo = s ? 0 : 3;
    const int ko = s ? 3 : 0;

    int p = 0;
    for (int blk = 0; blk < NBK; ++blk) {
        // stage next block (into the buffer last read two blocks ago; all
        // threads have passed the last mid-step barrier of blk-1, so reads
        // of that buffer are complete)
        if (blk + 1 < NBK) {
            unsigned dst = (blk & 1) ? xg_s0 : xg_s1;     // buffer (blk+1)&1
            const char* src = xg_gbase + (size_t)(blk + 1) * BK * G3 * 2;
            #pragma unroll
            for (int c = 0; c < 3; c++)
                cpa16(dst + (tid + 64 * c) * 16, src + (tid + 64 * c) * 16);
        }
        cpa_commit();
        cpa_wait1();           // block blk's data landed
        __syncthreads();       // visible to all threads

        const __half* xb = &xg_sh[blk & 1][0][0];

        #pragma unroll
        for (int tt = 0; tt < BK; ++tt) {
            // xg for this step (SMEM, issued early; used after mid barrier)
            float cur0 = __half2float(xb[tt * G3 + u]);
            float cur1 = __half2float(xb[tt * G3 + HH + u]);
            float cur2 = __half2float(xb[tt * G3 + 2 * HH + u]);

            // partial dots over this warp's k-half
            const ulonglong2* hp = (const ulonglong2*)&h_sh[32 * s];
            ull a[6] = {0ull, 0ull, 0ull, 0ull, 0ull, 0ull};
            #pragma unroll
            for (int j = 0; j < 8; j++) {
                ulonglong2 hv = hp[j];
                #pragma unroll
                for (int i = 0; i < 6; i++) {
                    a[i] = fma2(w[i][j].x, hv.x, a[i]);
                    a[i] = fma2(w[i][j].y, hv.y, a[i]);
                }
            }
            float prt[6];
            #pragma unroll
            for (int i = 0; i < 6; i++) prt[i] = hadd2(a[i]);

            part_sh[p][s][0][l] = prt[eo + 0];
            part_sh[p][s][1][l] = prt[eo + 1];
            part_sh[p][s][2][l] = prt[eo + 2];
            __syncthreads();

            float sr = prt[ko + 0] + part_sh[p][s ^ 1][0][l] + bhr;
            float sz = prt[ko + 1] + part_sh[p][s ^ 1][1][l] + bhz;
            float sh = prt[ko + 2] + part_sh[p][s ^ 1][2][l] + bhn;

            float rr = siga(cur0 + sr);
            float zz = siga(cur1 + sz);
            float nn = tanha(cur2 + rr * sh);
            hold = (1.f - zz) * nn + zz * hold;

            h_sh[u] = hold;
            __syncwarp();
            p ^= 1;
        }
    }
    __syncthreads();

    // ---- epilogue: backward GRU = ONE step from h=0 on x[:,T-1,:]; then fc ----
    {
        const int j = tid;
        const float* xl = x + ((size_t)b * TT + (TT - 1)) * DD;
        float xv[DD];
        #pragma unroll
        for (int k = 0; k < DD; k++) xv[k] = __ldg(xl + k);

        float ar  = __ldg(b_ih_b + j)          + __ldg(b_hh_b + j);
        float az  = __ldg(b_ih_b + HH + j)     + __ldg(b_hh_b + HH + j);
        float anx = __ldg(b_ih_b + 2 * HH + j);
        float anh = __ldg(b_hh_b + 2 * HH + j);
        const float* wr = w_ih_b + (size_t)j * DD;
        const float* wz = w_ih_b + (size_t)(HH + j) * DD;
        const float* wn = w_ih_b + (size_t)(2 * HH + j) * DD;
        #pragma unroll
        for (int k = 0; k < DD; k++) {
            ar  += __ldg(wr + k) * xv[k];
            az  += __ldg(wz + k) * xv[k];
            anx += __ldg(wn + k) * xv[k];
        }
        float rb = siga(ar);
        float zb = siga(az);
        float nb = tanha(anx + rb * anh);
        float hb = (1.f - zb) * nb;            // h_prev = 0

        red_sh[j] = h_sh[j] * __ldg(fc_w + j) + hb * __ldg(fc_w + HH + j);
    }
    __syncthreads();
    if (tid == 0) {
        float sum = __ldg(fc_b);
        #pragma unroll
        for (int k = 0; k < HH; k++) sum += red_sh[k];
        out[b] = sum;
    }
}

extern "C" void kernel_launch(void* const* d_in, const int* in_sizes, int n_in,
                              void* d_out, int out_size)
{
    const float* x      = (const float*)d_in[0];
    const float* w_ih_f = (const float*)d_in[1];
    const float* w_hh_f = (const float*)d_in[2];
    const float* b_ih_f = (const float*)d_in[3];
    const float* b_hh_f = (const float*)d_in[4];
    const float* w_ih_b = (const float*)d_in[5];
    /* d_in[6] = w_hh_b unused: backward direction starts from h=0 */
    const float* b_ih_b = (const float*)d_in[7];
    const float* b_hh_b = (const float*)d_in[8];
    const float* fc_w   = (const float*)d_in[9];
    const float* fc_b   = (const float*)d_in[10];

    xg_kernel<<<dim3(TT / PT, BB), G3>>>(x, w_ih_f, b_ih_f);
    gru_rec_kernel<<<BB, 64>>>(w_hh_f, b_hh_f, x,
                               w_ih_b, b_ih_b, b_hh_b,
                               fc_w, fc_b, (float*)d_out);
}